// round 6
// baseline (speedup 1.0000x reference)
#include <cuda_runtime.h>

#define N_NODES 40000
#define N_EDGES 640000
#define DIN 128
#define DH 128
#define DOUT 64

// ---------------- scratch (no allocations allowed) ----------------
__device__ int   g_is64;                 // 1 if edge_index is int64, 0 if int32
__device__ int   g_cnt[N_NODES];
__device__ int   g_rowptr[N_NODES + 1];
__device__ int   g_cursor[N_NODES];
__device__ int   g_esrc[N_EDGES];
__device__ float g_dinv[N_NODES];
__device__ float g_h1[(size_t)N_NODES * DH];     // x @ W1
__device__ float g_agg1[(size_t)N_NODES * DH];   // layer-1 aggregation (pre relu/bias)
__device__ float g_h2[(size_t)N_NODES * DOUT];   // relu(agg1+b1) @ W2

// ---------------- dtype detection ----------------
// Inspect first 4096 int32 pairs (16 KB — safe under both interpretations).
// int64 indices < 2^31  => every odd int32 word is 0.
// int32 indices uniform => odd words are random node ids, virtually surely nonzero.
__global__ void k_detect(const int* __restrict__ ei) {
    __shared__ int any_nz;
    if (threadIdx.x == 0) any_nz = 0;
    __syncthreads();
    int nz = 0;
    for (int i = threadIdx.x; i < 4096; i += blockDim.x)
        if (ei[2 * i + 1] != 0) nz = 1;
    if (nz) any_nz = 1;   // benign race: only writes 1
    __syncthreads();
    if (threadIdx.x == 0) g_is64 = any_nz ? 0 : 1;
}

__device__ __forceinline__ int edge_idx(const void* ei, int which, int e, int is64) {
    if (is64) return (int)((const long long*)ei)[(size_t)which * N_EDGES + e];
    return ((const int*)ei)[which * N_EDGES + e];
}

// ---------------- CSR build ----------------
__global__ void k_zero() {
    int i = blockIdx.x * blockDim.x + threadIdx.x;
    if (i < N_NODES) g_cnt[i] = 0;
}

__global__ void k_count(const void* __restrict__ ei) {
    int e = blockIdx.x * blockDim.x + threadIdx.x;
    if (e < N_EDGES) {
        int d = edge_idx(ei, 1, e, g_is64);
        if ((unsigned)d < N_NODES) atomicAdd(&g_cnt[d], 1);
    }
}

// one block, 1024 threads: exclusive scan of g_cnt -> rowptr/cursor, plus dinv
__global__ void k_scan() {
    __shared__ int sums[1024];
    const int t = threadIdx.x;
    const int CH = (N_NODES + 1023) / 1024;  // 40
    int beg = t * CH;
    int end = min(beg + CH, N_NODES);
    int s = 0;
    for (int i = beg; i < end; i++) s += g_cnt[i];
    sums[t] = s;
    __syncthreads();
    for (int off = 1; off < 1024; off <<= 1) {
        int v = (t >= off) ? sums[t - off] : 0;
        __syncthreads();
        sums[t] += v;
        __syncthreads();
    }
    int run = (t == 0) ? 0 : sums[t - 1];
    for (int i = beg; i < end; i++) {
        g_rowptr[i] = run;
        g_cursor[i] = run;
        int c = g_cnt[i];
        run += c;
        g_dinv[i] = rsqrtf((float)(c + 1));  // +1 self-loop
    }
    if (t == 1023) g_rowptr[N_NODES] = sums[1023];
}

__global__ void k_fill(const void* __restrict__ ei) {
    int e = blockIdx.x * blockDim.x + threadIdx.x;
    if (e < N_EDGES) {
        int is64 = g_is64;
        int d = edge_idx(ei, 1, e, is64);
        int s = edge_idx(ei, 0, e, is64);
        if ((unsigned)d < N_NODES && (unsigned)s < N_NODES) {
            int pos = atomicAdd(&g_cursor[d], 1);
            g_esrc[pos] = s;
        }
    }
}

// ---------------- tiled fp32 GEMM: C[M,BN] = op(A[M,128]) @ W[128,BN] ----------------
template <int BN, bool RELU_BIAS>
__global__ void k_gemm(const float* __restrict__ A, const float* __restrict__ W,
                       const float* __restrict__ bias, float* __restrict__ C) {
    constexpr int K = 128, BM = 64, BK = 16;
    constexpr int TX = BN / 4;
    constexpr int TY = 256 / TX;
    constexpr int RPT = BM / TY;

    __shared__ float As[BM][BK];
    __shared__ float Ws[BK][BN];
    __shared__ float bsh[K];

    const int tid = threadIdx.x;
    const int block_row = blockIdx.x * BM;
    const int tx = tid % TX;
    const int ty = tid / TX;

    if (RELU_BIAS) {
        if (tid < K) bsh[tid] = bias[tid];
        __syncthreads();
    }

    float acc[RPT][4];
#pragma unroll
    for (int r = 0; r < RPT; r++)
#pragma unroll
        for (int c = 0; c < 4; c++) acc[r][c] = 0.0f;

    for (int k0 = 0; k0 < K; k0 += BK) {
        {
            int row = tid >> 2;
            int kq = (tid & 3) * 4;
            float4 a = *(const float4*)(A + (size_t)(block_row + row) * K + k0 + kq);
            if (RELU_BIAS) {
                a.x = fmaxf(a.x + bsh[k0 + kq + 0], 0.0f);
                a.y = fmaxf(a.y + bsh[k0 + kq + 1], 0.0f);
                a.z = fmaxf(a.z + bsh[k0 + kq + 2], 0.0f);
                a.w = fmaxf(a.w + bsh[k0 + kq + 3], 0.0f);
            }
            *(float4*)&As[row][kq] = a;
        }
        constexpr int WLOADS = (BK * BN / 4) / 256;
#pragma unroll
        for (int L = 0; L < WLOADS; L++) {
            int idx = tid + L * 256;
            int r = idx / (BN / 4);
            int cq = (idx % (BN / 4)) * 4;
            *(float4*)&Ws[r][cq] = *(const float4*)(W + (size_t)(k0 + r) * BN + cq);
        }
        __syncthreads();

#pragma unroll
        for (int kk = 0; kk < BK; kk++) {
            float4 wv = *(const float4*)&Ws[kk][tx * 4];
#pragma unroll
            for (int r = 0; r < RPT; r++) {
                float a = As[ty * RPT + r][kk];
                acc[r][0] = fmaf(a, wv.x, acc[r][0]);
                acc[r][1] = fmaf(a, wv.y, acc[r][1]);
                acc[r][2] = fmaf(a, wv.z, acc[r][2]);
                acc[r][3] = fmaf(a, wv.w, acc[r][3]);
            }
        }
        __syncthreads();
    }

#pragma unroll
    for (int r = 0; r < RPT; r++) {
        float4 o = make_float4(acc[r][0], acc[r][1], acc[r][2], acc[r][3]);
        *(float4*)(C + (size_t)(block_row + ty * RPT + r) * BN + tx * 4) = o;
    }
}

// ---------------- gather aggregation, layer 1 (C=128): one warp per node ----------------
__global__ void k_gather1() {
    int node = (blockIdx.x * blockDim.x + threadIdx.x) >> 5;
    if (node >= N_NODES) return;
    int lane = threadIdx.x & 31;

    float dd = g_dinv[node];
    float self = dd * dd;
    float4 acc = ((const float4*)(g_h1 + (size_t)node * DH))[lane];
    acc.x *= self; acc.y *= self; acc.z *= self; acc.w *= self;

    int e = g_rowptr[node];
    int end = g_rowptr[node + 1];
    for (; e + 1 < end; e += 2) {
        int s0 = g_esrc[e], s1 = g_esrc[e + 1];
        float w0 = g_dinv[s0] * dd;
        float w1 = g_dinv[s1] * dd;
        float4 v0 = ((const float4*)(g_h1 + (size_t)s0 * DH))[lane];
        float4 v1 = ((const float4*)(g_h1 + (size_t)s1 * DH))[lane];
        acc.x = fmaf(v0.x, w0, fmaf(v1.x, w1, acc.x));
        acc.y = fmaf(v0.y, w0, fmaf(v1.y, w1, acc.y));
        acc.z = fmaf(v0.z, w0, fmaf(v1.z, w1, acc.z));
        acc.w = fmaf(v0.w, w0, fmaf(v1.w, w1, acc.w));
    }
    if (e < end) {
        int s0 = g_esrc[e];
        float w0 = g_dinv[s0] * dd;
        float4 v0 = ((const float4*)(g_h1 + (size_t)s0 * DH))[lane];
        acc.x = fmaf(v0.x, w0, acc.x);
        acc.y = fmaf(v0.y, w0, acc.y);
        acc.z = fmaf(v0.z, w0, acc.z);
        acc.w = fmaf(v0.w, w0, acc.w);
    }
    ((float4*)(g_agg1 + (size_t)node * DH))[lane] = acc;
}

// ---------------- gather aggregation, layer 2 (C=64): half-warp per node, + b2 ----------------
__global__ void k_gather2(const float* __restrict__ b2, float* __restrict__ out) {
    int gw = (blockIdx.x * blockDim.x + threadIdx.x) >> 5;
    int lane = threadIdx.x & 31;
    int node = gw * 2 + (lane >> 4);
    if (node >= N_NODES) return;
    int l = lane & 15;  // 16 lanes x float4 = 64 floats

    float dd = g_dinv[node];
    float self = dd * dd;
    float4 acc = ((const float4*)(g_h2 + (size_t)node * DOUT))[l];
    acc.x *= self; acc.y *= self; acc.z *= self; acc.w *= self;

    int e = g_rowptr[node];
    int end = g_rowptr[node + 1];
    for (; e + 1 < end; e += 2) {
        int s0 = g_esrc[e], s1 = g_esrc[e + 1];
        float w0 = g_dinv[s0] * dd;
        float w1 = g_dinv[s1] * dd;
        float4 v0 = ((const float4*)(g_h2 + (size_t)s0 * DOUT))[l];
        float4 v1 = ((const float4*)(g_h2 + (size_t)s1 * DOUT))[l];
        acc.x = fmaf(v0.x, w0, fmaf(v1.x, w1, acc.x));
        acc.y = fmaf(v0.y, w0, fmaf(v1.y, w1, acc.y));
        acc.z = fmaf(v0.z, w0, fmaf(v1.z, w1, acc.z));
        acc.w = fmaf(v0.w, w0, fmaf(v1.w, w1, acc.w));
    }
    if (e < end) {
        int s0 = g_esrc[e];
        float w0 = g_dinv[s0] * dd;
        float4 v0 = ((const float4*)(g_h2 + (size_t)s0 * DOUT))[l];
        acc.x = fmaf(v0.x, w0, acc.x);
        acc.y = fmaf(v0.y, w0, acc.y);
        acc.z = fmaf(v0.z, w0, acc.z);
        acc.w = fmaf(v0.w, w0, acc.w);
    }
    float4 b = ((const float4*)b2)[l];
    acc.x += b.x; acc.y += b.y; acc.z += b.z; acc.w += b.w;
    ((float4*)(out + (size_t)node * DOUT))[l] = acc;
}

// ---------------- launch ----------------
extern "C" void kernel_launch(void* const* d_in, const int* in_sizes, int n_in,
                              void* d_out, int out_size) {
    const float* x  = (const float*)d_in[0];
    const void*  ei = d_in[1];                 // int32 or int64 — detected on device
    const float* W1 = (const float*)d_in[2];
    const float* b1 = (const float*)d_in[3];
    const float* W2 = (const float*)d_in[4];
    const float* b2 = (const float*)d_in[5];
    float*       out = (float*)d_out;

    float *h1, *agg1, *h2;
    cudaGetSymbolAddress((void**)&h1, g_h1);
    cudaGetSymbolAddress((void**)&agg1, g_agg1);
    cudaGetSymbolAddress((void**)&h2, g_h2);

    const int T = 256;

    // dtype detection + CSR build + normalization
    k_detect<<<1, 256>>>((const int*)ei);
    k_zero<<<(N_NODES + T - 1) / T, T>>>();
    k_count<<<(N_EDGES + T - 1) / T, T>>>(ei);
    k_scan<<<1, 1024>>>();
    k_fill<<<(N_EDGES + T - 1) / T, T>>>(ei);

    // layer 1: h1 = x @ W1 ; agg1 = normalized aggregation (incl. self loop)
    k_gemm<DH, false><<<N_NODES / 64, T>>>(x, W1, nullptr, h1);
    k_gather1<<<(N_NODES * 32 + T - 1) / T, T>>>();

    // layer 2: h2 = relu(agg1 + b1) @ W2 ; out = aggregation + b2
    k_gemm<DOUT, true><<<N_NODES / 64, T>>>(agg1, W2, b1, h2);
    k_gather2<<<(N_NODES / 2 * 32 + T - 1) / T, T>>>(b2, out);
}

// round 7
// speedup vs baseline: 1.5625x; 1.5625x over previous
#include <cuda_runtime.h>

#define N_NODES 40000
#define N_EDGES 640000
#define DIN 128
#define DH 128
#define DOUT 64

#define SCAN_B 256
#define SCAN_NB ((N_NODES + SCAN_B - 1) / SCAN_B)   // 157

// ---------------- scratch (no allocations allowed) ----------------
__device__ int   g_is64;                 // 1 if edge_index is int64, 0 if int32
__device__ int   g_cnt[N_NODES];
__device__ int   g_rowptr[N_NODES + 1];
__device__ int   g_cursor[N_NODES];
__device__ int   g_bsum[SCAN_B];
__device__ int   g_boff[SCAN_B];
__device__ int   g_esrc[N_EDGES];
__device__ float g_dinv[N_NODES];
__device__ float g_h1[(size_t)N_NODES * DH];     // x @ W1
__device__ float g_agg1[(size_t)N_NODES * DH];   // layer-1 aggregation (pre relu/bias)
__device__ float g_h2[(size_t)N_NODES * DOUT];   // relu(agg1+b1) @ W2

// ---------------- dtype detection ----------------
// Inspect first 4096 int32 pairs (16 KB — safe under both interpretations).
// int64 indices < 2^31  => every odd int32 word is 0.
// int32 indices uniform => odd words are random node ids, virtually surely nonzero.
__global__ void k_detect(const int* __restrict__ ei) {
    __shared__ int any_nz;
    if (threadIdx.x == 0) any_nz = 0;
    __syncthreads();
    int nz = 0;
    for (int i = threadIdx.x; i < 4096; i += blockDim.x)
        if (ei[2 * i + 1] != 0) nz = 1;
    if (nz) any_nz = 1;   // benign race: only writes 1
    __syncthreads();
    if (threadIdx.x == 0) g_is64 = any_nz ? 0 : 1;
}

__device__ __forceinline__ int edge_idx(const void* ei, int which, int e, int is64) {
    if (is64) return (int)((const long long*)ei)[(size_t)which * N_EDGES + e];
    return ((const int*)ei)[which * N_EDGES + e];
}

// ---------------- CSR build ----------------
__global__ void k_zero() {
    int i = blockIdx.x * blockDim.x + threadIdx.x;
    if (i < N_NODES) g_cnt[i] = 0;
}

__global__ void k_count(const void* __restrict__ ei) {
    int e = blockIdx.x * blockDim.x + threadIdx.x;
    if (e < N_EDGES) {
        int d = edge_idx(ei, 1, e, g_is64);
        if ((unsigned)d < N_NODES) atomicAdd(&g_cnt[d], 1);
    }
}

// ---- 3-phase exclusive scan of g_cnt -> rowptr/cursor (+ dinv) ----
// Phase A: per-block inclusive scan; local-exclusive to rowptr, totals to g_bsum.
__global__ void k_scan_a() {
    __shared__ int sh[SCAN_B];
    int i = blockIdx.x * SCAN_B + threadIdx.x;
    int v = (i < N_NODES) ? g_cnt[i] : 0;
    sh[threadIdx.x] = v;
    __syncthreads();
#pragma unroll
    for (int off = 1; off < SCAN_B; off <<= 1) {
        int t = (threadIdx.x >= off) ? sh[threadIdx.x - off] : 0;
        __syncthreads();
        sh[threadIdx.x] += t;
        __syncthreads();
    }
    if (i < N_NODES) g_rowptr[i] = sh[threadIdx.x] - v;   // local exclusive
    if (threadIdx.x == SCAN_B - 1) g_bsum[blockIdx.x] = sh[threadIdx.x];
}

// Phase B: single block scans the SCAN_NB block totals.
__global__ void k_scan_b() {
    __shared__ int sh[SCAN_B];
    int v = (threadIdx.x < SCAN_NB) ? g_bsum[threadIdx.x] : 0;
    sh[threadIdx.x] = v;
    __syncthreads();
#pragma unroll
    for (int off = 1; off < SCAN_B; off <<= 1) {
        int t = (threadIdx.x >= off) ? sh[threadIdx.x - off] : 0;
        __syncthreads();
        sh[threadIdx.x] += t;
        __syncthreads();
    }
    if (threadIdx.x < SCAN_NB) g_boff[threadIdx.x] = sh[threadIdx.x] - v;  // exclusive
    if (threadIdx.x == SCAN_NB - 1) g_rowptr[N_NODES] = sh[threadIdx.x];   // grand total
}

// Phase C: add block offsets; emit cursor + dinv.
__global__ void k_scan_c() {
    int i = blockIdx.x * SCAN_B + threadIdx.x;
    if (i < N_NODES) {
        int r = g_rowptr[i] + g_boff[blockIdx.x];
        g_rowptr[i] = r;
        g_cursor[i] = r;
        g_dinv[i] = rsqrtf((float)(g_cnt[i] + 1));   // +1 self-loop
    }
}

__global__ void k_fill(const void* __restrict__ ei) {
    int e = blockIdx.x * blockDim.x + threadIdx.x;
    if (e < N_EDGES) {
        int is64 = g_is64;
        int d = edge_idx(ei, 1, e, is64);
        int s = edge_idx(ei, 0, e, is64);
        if ((unsigned)d < N_NODES && (unsigned)s < N_NODES) {
            int pos = atomicAdd(&g_cursor[d], 1);
            g_esrc[pos] = s;
        }
    }
}

// ---------------- tiled fp32 GEMM: C[M,BN] = op(A[M,128]) @ W[128,BN] ----------------
template <int BN, bool RELU_BIAS>
__global__ void k_gemm(const float* __restrict__ A, const float* __restrict__ W,
                       const float* __restrict__ bias, float* __restrict__ C) {
    constexpr int K = 128, BM = 64, BK = 16;
    constexpr int TX = BN / 4;
    constexpr int TY = 256 / TX;
    constexpr int RPT = BM / TY;

    __shared__ float As[BM][BK];
    __shared__ float Ws[BK][BN];
    __shared__ float bsh[K];

    const int tid = threadIdx.x;
    const int block_row = blockIdx.x * BM;
    const int tx = tid % TX;
    const int ty = tid / TX;

    if (RELU_BIAS) {
        if (tid < K) bsh[tid] = bias[tid];
        __syncthreads();
    }

    float acc[RPT][4];
#pragma unroll
    for (int r = 0; r < RPT; r++)
#pragma unroll
        for (int c = 0; c < 4; c++) acc[r][c] = 0.0f;

    for (int k0 = 0; k0 < K; k0 += BK) {
        {
            int row = tid >> 2;
            int kq = (tid & 3) * 4;
            float4 a = *(const float4*)(A + (size_t)(block_row + row) * K + k0 + kq);
            if (RELU_BIAS) {
                a.x = fmaxf(a.x + bsh[k0 + kq + 0], 0.0f);
                a.y = fmaxf(a.y + bsh[k0 + kq + 1], 0.0f);
                a.z = fmaxf(a.z + bsh[k0 + kq + 2], 0.0f);
                a.w = fmaxf(a.w + bsh[k0 + kq + 3], 0.0f);
            }
            *(float4*)&As[row][kq] = a;
        }
        constexpr int WLOADS = (BK * BN / 4) / 256;
#pragma unroll
        for (int L = 0; L < WLOADS; L++) {
            int idx = tid + L * 256;
            int r = idx / (BN / 4);
            int cq = (idx % (BN / 4)) * 4;
            *(float4*)&Ws[r][cq] = *(const float4*)(W + (size_t)(k0 + r) * BN + cq);
        }
        __syncthreads();

#pragma unroll
        for (int kk = 0; kk < BK; kk++) {
            float4 wv = *(const float4*)&Ws[kk][tx * 4];
#pragma unroll
            for (int r = 0; r < RPT; r++) {
                float a = As[ty * RPT + r][kk];
                acc[r][0] = fmaf(a, wv.x, acc[r][0]);
                acc[r][1] = fmaf(a, wv.y, acc[r][1]);
                acc[r][2] = fmaf(a, wv.z, acc[r][2]);
                acc[r][3] = fmaf(a, wv.w, acc[r][3]);
            }
        }
        __syncthreads();
    }

#pragma unroll
    for (int r = 0; r < RPT; r++) {
        float4 o = make_float4(acc[r][0], acc[r][1], acc[r][2], acc[r][3]);
        *(float4*)(C + (size_t)(block_row + ty * RPT + r) * BN + tx * 4) = o;
    }
}

// ---------------- gather aggregation, layer 1 (C=128): one warp per node ----------------
__global__ void k_gather1() {
    int node = (blockIdx.x * blockDim.x + threadIdx.x) >> 5;
    if (node >= N_NODES) return;
    int lane = threadIdx.x & 31;

    float dd = g_dinv[node];
    float self = dd * dd;
    float4 acc = ((const float4*)(g_h1 + (size_t)node * DH))[lane];
    acc.x *= self; acc.y *= self; acc.z *= self; acc.w *= self;

    int e = g_rowptr[node];
    int end = g_rowptr[node + 1];
    for (; e + 1 < end; e += 2) {
        int s0 = g_esrc[e], s1 = g_esrc[e + 1];
        float w0 = g_dinv[s0] * dd;
        float w1 = g_dinv[s1] * dd;
        float4 v0 = ((const float4*)(g_h1 + (size_t)s0 * DH))[lane];
        float4 v1 = ((const float4*)(g_h1 + (size_t)s1 * DH))[lane];
        acc.x = fmaf(v0.x, w0, fmaf(v1.x, w1, acc.x));
        acc.y = fmaf(v0.y, w0, fmaf(v1.y, w1, acc.y));
        acc.z = fmaf(v0.z, w0, fmaf(v1.z, w1, acc.z));
        acc.w = fmaf(v0.w, w0, fmaf(v1.w, w1, acc.w));
    }
    if (e < end) {
        int s0 = g_esrc[e];
        float w0 = g_dinv[s0] * dd;
        float4 v0 = ((const float4*)(g_h1 + (size_t)s0 * DH))[lane];
        acc.x = fmaf(v0.x, w0, acc.x);
        acc.y = fmaf(v0.y, w0, acc.y);
        acc.z = fmaf(v0.z, w0, acc.z);
        acc.w = fmaf(v0.w, w0, acc.w);
    }
    ((float4*)(g_agg1 + (size_t)node * DH))[lane] = acc;
}

// ---------------- gather aggregation, layer 2 (C=64): half-warp per node, + b2 ----------------
__global__ void k_gather2(const float* __restrict__ b2, float* __restrict__ out) {
    int gw = (blockIdx.x * blockDim.x + threadIdx.x) >> 5;
    int lane = threadIdx.x & 31;
    int node = gw * 2 + (lane >> 4);
    if (node >= N_NODES) return;
    int l = lane & 15;  // 16 lanes x float4 = 64 floats

    float dd = g_dinv[node];
    float self = dd * dd;
    float4 acc = ((const float4*)(g_h2 + (size_t)node * DOUT))[l];
    acc.x *= self; acc.y *= self; acc.z *= self; acc.w *= self;

    int e = g_rowptr[node];
    int end = g_rowptr[node + 1];
    for (; e + 1 < end; e += 2) {
        int s0 = g_esrc[e], s1 = g_esrc[e + 1];
        float w0 = g_dinv[s0] * dd;
        float w1 = g_dinv[s1] * dd;
        float4 v0 = ((const float4*)(g_h2 + (size_t)s0 * DOUT))[l];
        float4 v1 = ((const float4*)(g_h2 + (size_t)s1 * DOUT))[l];
        acc.x = fmaf(v0.x, w0, fmaf(v1.x, w1, acc.x));
        acc.y = fmaf(v0.y, w0, fmaf(v1.y, w1, acc.y));
        acc.z = fmaf(v0.z, w0, fmaf(v1.z, w1, acc.z));
        acc.w = fmaf(v0.w, w0, fmaf(v1.w, w1, acc.w));
    }
    if (e < end) {
        int s0 = g_esrc[e];
        float w0 = g_dinv[s0] * dd;
        float4 v0 = ((const float4*)(g_h2 + (size_t)s0 * DOUT))[l];
        acc.x = fmaf(v0.x, w0, acc.x);
        acc.y = fmaf(v0.y, w0, acc.y);
        acc.z = fmaf(v0.z, w0, acc.z);
        acc.w = fmaf(v0.w, w0, acc.w);
    }
    float4 b = ((const float4*)b2)[l];
    acc.x += b.x; acc.y += b.y; acc.z += b.z; acc.w += b.w;
    ((float4*)(out + (size_t)node * DOUT))[l] = acc;
}

// ---------------- launch ----------------
extern "C" void kernel_launch(void* const* d_in, const int* in_sizes, int n_in,
                              void* d_out, int out_size) {
    const float* x  = (const float*)d_in[0];
    const void*  ei = d_in[1];                 // int32 or int64 — detected on device
    const float* W1 = (const float*)d_in[2];
    const float* b1 = (const float*)d_in[3];
    const float* W2 = (const float*)d_in[4];
    const float* b2 = (const float*)d_in[5];
    float*       out = (float*)d_out;

    float *h1, *agg1, *h2;
    cudaGetSymbolAddress((void**)&h1, g_h1);
    cudaGetSymbolAddress((void**)&agg1, g_agg1);
    cudaGetSymbolAddress((void**)&h2, g_h2);

    const int T = 256;

    // dtype detection + CSR build + normalization
    k_detect<<<1, 256>>>((const int*)ei);
    k_zero<<<(N_NODES + T - 1) / T, T>>>();
    k_count<<<(N_EDGES + T - 1) / T, T>>>(ei);
    k_scan_a<<<SCAN_NB, SCAN_B>>>();
    k_scan_b<<<1, SCAN_B>>>();
    k_scan_c<<<SCAN_NB, SCAN_B>>>();
    k_fill<<<(N_EDGES + T - 1) / T, T>>>(ei);

    // layer 1: h1 = x @ W1 ; agg1 = normalized aggregation (incl. self loop)
    k_gemm<DH, false><<<N_NODES / 64, T>>>(x, W1, nullptr, h1);
    k_gather1<<<(N_NODES * 32 + T - 1) / T, T>>>();

    // layer 2: h2 = relu(agg1 + b1) @ W2 ; out = aggregation + b2
    k_gemm<DOUT, true><<<N_NODES / 64, T>>>(agg1, W2, b1, h2);
    k_gather2<<<(N_NODES / 2 * 32 + T - 1) / T, T>>>(b2, out);
}